// round 12
// baseline (speedup 1.0000x reference)
#include <cuda_runtime.h>

// Decoder: y_{t+1} = y_t + cutoff * tanh(dt * MLP_b(y_t) / cutoff), per-batch weights.
// R11 int16 design (256x256 persistent CTAs, exact ReLU sparsity, biased PRMT dequant,
// per-4-row deferred bias correction) + packed f32x2 FMA (fma.rn.f32x2, 2 MACs/inst)
// for the accumulators: mainloop FMA instruction count halves on the issue-bound path.

#define NB 256
#define NC 16
#define NH 256
#define NT 1000
#define TB 8

// Quantized prop weights: biased uint16 (int16 value + 32768), layout [b][l][k][j].
__device__ __align__(16) unsigned short g_pwq[(size_t)NB * 2 * NH * NH];
__device__ float g_scl[NB * 2 * NH];   // per-row scale s = rowmax/32767

// ---- packed f32x2 helpers ----
__device__ __forceinline__ unsigned long long pack2(float lo, float hi)
{
    unsigned long long r;
    asm("mov.b64 %0, {%1, %2};" : "=l"(r) : "f"(lo), "f"(hi));
    return r;
}
// two biased dequants (2^23 + u16) from one u32, packed into a f32x2 pair
__device__ __forceinline__ unsigned long long cvpair(unsigned u)
{
    unsigned long long r;
    asm("{\n\t"
        ".reg .b32 lo, hi;\n\t"
        "prmt.b32 lo, %1, 0x4B000000, 0x7410;\n\t"
        "prmt.b32 hi, %1, 0x4B000000, 0x7432;\n\t"
        "mov.b64 %0, {lo, hi};\n\t"
        "}" : "=l"(r) : "r"(u));
    return r;
}
__device__ __forceinline__ void ffma2(unsigned long long& a,
                                      unsigned long long x,
                                      unsigned long long y)
{
    asm("fma.rn.f32x2 %0, %1, %2, %0;" : "+l"(a) : "l"(x), "l"(y));
}
// biased row FMA: 8 outputs as 4 f32x2 accumulators, FFMA2 only.
__device__ __forceinline__ void rowfma2_b(unsigned long long e2, uint4 w,
                                          unsigned long long A[4])
{
    ffma2(A[0], e2, cvpair(w.x));
    ffma2(A[1], e2, cvpair(w.y));
    ffma2(A[2], e2, cvpair(w.z));
    ffma2(A[3], e2, cvpair(w.w));
}
// remove accumulated bias for a group with packed activation-sum es2.
__device__ __forceinline__ void corr2(unsigned long long es2,
                                      unsigned long long nb2,
                                      unsigned long long A[4])
{
    ffma2(A[0], es2, nb2);
    ffma2(A[1], es2, nb2);
    ffma2(A[2], es2, nb2);
    ffma2(A[3], es2, nb2);
}

// ---- pre-pass: quantize 32 rows per block (coalesced stage through SMEM) ----
__global__ __launch_bounds__(256)
void quant_kernel(const float* __restrict__ pw)
{
    __shared__ float buf[32 * NH];            // 32 KB
    const int blk = blockIdx.x;               // NB*2*8 = 4096 blocks
    const int rb  = blk & 7;                  // 32-row block within matrix
    const int bl  = blk >> 3;                 // b*2 + l
    const float* src = pw + (size_t)bl * NH * NH + (size_t)rb * 32 * NH;
    const int tid = threadIdx.x;

    for (int idx = tid; idx < 32 * NH / 4; idx += 256)
        reinterpret_cast<float4*>(buf)[idx] =
            reinterpret_cast<const float4*>(src)[idx];
    __syncthreads();

    const int lane = tid & 31;
    const int wrp  = tid >> 5;
#pragma unroll
    for (int r = wrp * 4; r < wrp * 4 + 4; r++) {
        float mx = 0.f;
        for (int j = lane; j < NH; j += 32)
            mx = fmaxf(mx, fabsf(buf[r * NH + j]));
#pragma unroll
        for (int o = 16; o; o >>= 1)
            mx = fmaxf(mx, __shfl_xor_sync(0xffffffffu, mx, o));
        const float inv = (mx > 0.f) ? 32767.f / mx : 0.f;
        const int grow = rb * 32 + r;
        if (lane == 0)
            g_scl[bl * NH + grow] = (mx > 0.f) ? mx / 32767.f : 0.f;
        unsigned q[4];
#pragma unroll
        for (int p = 0; p < 4; p++) {
            int j = lane * 8 + p * 2;
            int va = __float2int_rn(buf[r * NH + j]     * inv);
            int vb = __float2int_rn(buf[r * NH + j + 1] * inv);
            va = max(-32767, min(32767, va)) + 32768;
            vb = max(-32767, min(32767, vb)) + 32768;
            q[p] = (unsigned)va | ((unsigned)vb << 16);
        }
        uint4 pack;
        pack.x = q[0]; pack.y = q[1]; pack.z = q[2]; pack.w = q[3];
        *reinterpret_cast<uint4*>(
            &g_pwq[((size_t)bl * NH + grow) * NH + lane * 8]) = pack;
    }
}

__global__ __launch_bounds__(256, 2)
void decoder_kernel(const float* __restrict__ y0,
                    const float* __restrict__ in_w,    // [B, C, H]
                    const float* __restrict__ in_b,    // [B, H]
                    const float* __restrict__ out_w,   // [B, H, C]
                    const float* __restrict__ out_b,   // [B, C]
                    const float* __restrict__ pb,      // [B, 2, H]
                    const float* __restrict__ cutoff,  // [1]
                    float* __restrict__ out)           // [B, C, T]
{
    __shared__ float  in_s[NC * NH];     // [c][i]
    __shared__ float  out_s[NH * NC];    // [k][c]
    __shared__ float2 act[NH];           // compacted (scaled h, row byte-offset bits)
    __shared__ __align__(16) int cnt_s[8];
    __shared__ float  ys[NC];
    __shared__ float  po8[8 * NH];       // [group 0..7][output i] partials
    __shared__ float  po_s[256];         // out-layer partials [g16][c]
    __shared__ float  stage[NC][TB];

    const int b    = blockIdx.x;
    const int i    = threadIdx.x;
    const int lane = i & 31;
    const int wid  = i >> 5;   // warp = row group 0..7

    // ---- preload per-batch small weights into SMEM ----
    const float* inwb  = in_w  + (size_t)b * NC * NH;
    const float* outwb = out_w + (size_t)b * NH * NC;

#pragma unroll
    for (int c = 0; c < NC; c++)
        in_s[c * NH + i] = inwb[c * NH + i];

#pragma unroll
    for (int q = 0; q < 4; q++) {
        float4 v = *reinterpret_cast<const float4*>(outwb + i * NC + q * 4);
        *reinterpret_cast<float4*>(&out_s[i * NC + q * 4]) = v;
    }

    const float bin = in_b[(size_t)b * NH + i];
    const float bp0 = pb[(size_t)b * 2 * NH + i];
    const float bp1 = pb[(size_t)b * 2 * NH + NH + i];
    const float ob  = (i < NC) ? out_b[(size_t)b * NC + i] : 0.f;
    const float cut = cutoff[0];
    const float dt  = 1e-6f;
    const float s0r = g_scl[(b * 2 + 0) * NH + i];
    const float s1r = g_scl[(b * 2 + 1) * NH + i];

    if (i < NC) ys[i] = y0[(size_t)b * NC + i];

    const unsigned short* pwq0 = &g_pwq[(size_t)(b * 2 + 0) * NH * NH];
    const unsigned short* pwq1 = &g_pwq[(size_t)(b * 2 + 1) * NH * NH];
    float* outg = out + (size_t)b * NC * NT;

    const unsigned long long NB2 = pack2(-8421376.0f, -8421376.0f);
    int na = 0;  // active count (uniform across CTA after compact)

    // Deterministic compaction; vectorized count read (2x LDS.128).
    auto compact = [&](float rawh, float storeval, int koffbits) {
        bool nz = rawh > 0.f;
        unsigned bal = __ballot_sync(0xffffffffu, nz);
        if (lane == 0) cnt_s[wid] = __popc(bal);
        __syncthreads();
        int4 c0 = *reinterpret_cast<const int4*>(&cnt_s[0]);
        int4 c1 = *reinterpret_cast<const int4*>(&cnt_s[4]);
        na = ((c0.x + c0.y) + (c0.z + c0.w)) + ((c1.x + c1.y) + (c1.z + c1.w));
        int base = 0;
        if (wid > 0) base += c0.x;
        if (wid > 1) base += c0.y;
        if (wid > 2) base += c0.z;
        if (wid > 3) base += c0.w;
        if (wid > 4) base += c1.x;
        if (wid > 5) base += c1.y;
        if (wid > 6) base += c1.z;
        if (nz) {
            int pos = base + __popc(bal & ((1u << lane) - 1u));
            act[pos] = make_float2(storeval, __int_as_float(koffbits));
        }
        __syncthreads();
    };

    // Sparse int16 matvec: warp wid owns rows m ≡ wid (mod 8); thread owns outputs
    // [lane*8 .. lane*8+7] as 4 f32x2 accumulators. One LDG.128 per (thread,row);
    // the warp covers the full 512B int16 row contiguously. Unroll 8 rows; biased
    // FFMA2 + per-4-row packed bias correction.
    auto prop_layer = [&](const unsigned short* wq, float bias,
                          float snext, bool last) {
        const char* bo = reinterpret_cast<const char*>(wq) + (size_t)(lane * 16);
        unsigned long long A[4];
#pragma unroll
        for (int z = 0; z < 4; z++) A[z] = pack2(0.f, 0.f);
        int m = wid;
        for (; m + 56 < na; m += 64) {
            float2 e[8];
            uint4  w[8];
#pragma unroll
            for (int z = 0; z < 8; z++)
                e[z] = act[m + z * 8];
#pragma unroll
            for (int z = 0; z < 8; z++)
                w[z] = *reinterpret_cast<const uint4*>(bo + __float_as_int(e[z].y));
            // group 0: rows 0..3 biased, then one packed correction
            rowfma2_b(pack2(e[0].x, e[0].x), w[0], A);
            rowfma2_b(pack2(e[1].x, e[1].x), w[1], A);
            rowfma2_b(pack2(e[2].x, e[2].x), w[2], A);
            rowfma2_b(pack2(e[3].x, e[3].x), w[3], A);
            {
                float es = (e[0].x + e[1].x) + (e[2].x + e[3].x);
                corr2(pack2(es, es), NB2, A);
            }
            // group 1: rows 4..7
            rowfma2_b(pack2(e[4].x, e[4].x), w[4], A);
            rowfma2_b(pack2(e[5].x, e[5].x), w[5], A);
            rowfma2_b(pack2(e[6].x, e[6].x), w[6], A);
            rowfma2_b(pack2(e[7].x, e[7].x), w[7], A);
            {
                float es = (e[4].x + e[5].x) + (e[6].x + e[7].x);
                corr2(pack2(es, es), NB2, A);
            }
        }
        for (; m < na; m += 8) {   // tail: biased row + immediate per-row correction
            float2 e = act[m];
            uint4  w = *reinterpret_cast<const uint4*>(bo + __float_as_int(e.y));
            unsigned long long e2 = pack2(e.x, e.x);
            rowfma2_b(e2, w, A);
            corr2(e2, NB2, A);
        }
        // partials: outputs lane*8..+7 contiguous (pair lo = even output)
        unsigned long long* dstu =
            reinterpret_cast<unsigned long long*>(&po8[wid * NH + lane * 8]);
        dstu[0] = A[0]; dstu[1] = A[1]; dstu[2] = A[2]; dstu[3] = A[3];
        __syncthreads();
        float h = bias;
#pragma unroll
        for (int g = 0; g < 8; g++) h += po8[g * NH + i];
        h = fmaxf(h, 0.f);
        if (last) compact(h, h, i << 10);          // raw, feeds fp32 out_s
        else      compact(h, h * snext, i << 9);   // scaled, feeds int16 layer
    };

    __syncthreads();

    for (int t = 0; t < NT; t++) {
        // ---- input layer (all SMEM) ----
        float acc = bin;
#pragma unroll
        for (int c = 0; c < NC; c++)
            acc = fmaf(ys[c], in_s[c * NH + i], acc);
        acc = fmaxf(acc, 0.f);
        compact(acc, acc * s0r, i << 9);   // int16 row stride = 512 B

        // ---- two prop layers (sparse int16 rows) ----
        prop_layer(pwq0, bp0, s1r, false);
        prop_layer(pwq1, bp1, 0.f, true);

        // ---- output layer (SMEM, sparse over k) ----
        {
            int c = i & 15, g16 = i >> 4;
            float p = 0.f;
            for (int m = g16; m < na; m += 16) {
                float2 e = act[m];
                // koffbits = k<<10 -> out_s index k*16 + c = (bits>>6) + c
                p = fmaf(e.x, out_s[(__float_as_int(e.y) >> 6) + c], p);
            }
            po_s[i] = p;
        }
        __syncthreads();

        if (i < NC) {
            float f = ob;
#pragma unroll
            for (int g16 = 0; g16 < 16; g16++) f += po_s[g16 * 16 + i];
            float yn = ys[i] + cut * tanhf(dt * f / cut);
            ys[i] = yn;
            stage[i][t & (TB - 1)] = yn;
        }
        __syncthreads();

        // coalesced flush every TB steps
        if ((t & (TB - 1)) == (TB - 1) && i < NC * TB) {
            int c = i >> 3, u = i & 7;
            outg[c * NT + (t - (TB - 1)) + u] = stage[c][u];
        }
    }
}

extern "C" void kernel_launch(void* const* d_in, const int* in_sizes, int n_in,
                              void* d_out, int out_size)
{
    (void)in_sizes; (void)n_in; (void)out_size;
    quant_kernel<<<NB * 2 * 8, 256>>>((const float*)d_in[5]);  // prop_weight
    decoder_kernel<<<NB, 256>>>(
        (const float*)d_in[0],   // y0
        (const float*)d_in[1],   // in_weight
        (const float*)d_in[2],   // in_bias
        (const float*)d_in[3],   // out_weight
        (const float*)d_in[4],   // out_bias
        (const float*)d_in[6],   // prop_bias
        (const float*)d_in[7],   // cutoff
        (float*)d_out);
}

// round 13
// speedup vs baseline: 1.1915x; 1.1915x over previous
#include <cuda_runtime.h>

// Decoder: y_{t+1} = y_t + cutoff * tanh(dt * MLP_b(y_t) / cutoff), per-batch weights.
// R11 int16 design (256x256 persistent CTAs, exact ReLU sparsity, biased PRMT dequant,
// per-4-row deferred bias correction) + 2-stage software pipeline in the sparse matvec:
// 4-row chunks with ping-pong register buffers so chunk c+1's LDG latency overlaps
// chunk c's PRMT/FFMA work. Scalar FFMA path (f32x2 regressed in R12: reg-pair pressure).

#define NB 256
#define NC 16
#define NH 256
#define NT 1000
#define TB 8

// Quantized prop weights: biased uint16 (int16 value + 32768), layout [b][l][k][j].
__device__ __align__(16) unsigned short g_pwq[(size_t)NB * 2 * NH * NH];
__device__ float g_scl[NB * 2 * NH];   // per-row scale s = rowmax/32767

// ---- dequant helpers ----
__device__ __forceinline__ float cvlo_b(unsigned u)
{   // u16 placed in mantissa of 2^23 -> exact float 2^23 + u
    return __uint_as_float(__byte_perm(u, 0x4B000000u, 0x7410));
}
__device__ __forceinline__ float cvhi_b(unsigned u)
{
    return __uint_as_float(__byte_perm(u, 0x4B000000u, 0x7432));
}
__device__ __forceinline__ float cvlo(unsigned u) { return cvlo_b(u) - 8421376.0f; }
__device__ __forceinline__ float cvhi(unsigned u) { return cvhi_b(u) - 8421376.0f; }

// biased row FMA: 8 outputs, FFMA only (bias removed later).
__device__ __forceinline__ void rowfma_b(float e, uint4 w, float a[8])
{
    a[0] = fmaf(e, cvlo_b(w.x), a[0]);
    a[1] = fmaf(e, cvhi_b(w.x), a[1]);
    a[2] = fmaf(e, cvlo_b(w.y), a[2]);
    a[3] = fmaf(e, cvhi_b(w.y), a[3]);
    a[4] = fmaf(e, cvlo_b(w.z), a[4]);
    a[5] = fmaf(e, cvhi_b(w.z), a[5]);
    a[6] = fmaf(e, cvlo_b(w.w), a[6]);
    a[7] = fmaf(e, cvhi_b(w.w), a[7]);
}
// remove accumulated bias for a 4-row group with activation-sum es (FFMA-imm).
__device__ __forceinline__ void corr(float es, float a[8])
{
#pragma unroll
    for (int j = 0; j < 8; j++)
        a[j] = fmaf(es, -8421376.0f, a[j]);
}
// exact row FMA for tail rows.
__device__ __forceinline__ void rowfma(float e, uint4 w, float a[8])
{
    a[0] = fmaf(e, cvlo(w.x), a[0]);
    a[1] = fmaf(e, cvhi(w.x), a[1]);
    a[2] = fmaf(e, cvlo(w.y), a[2]);
    a[3] = fmaf(e, cvhi(w.y), a[3]);
    a[4] = fmaf(e, cvlo(w.z), a[4]);
    a[5] = fmaf(e, cvhi(w.z), a[5]);
    a[6] = fmaf(e, cvlo(w.w), a[6]);
    a[7] = fmaf(e, cvhi(w.w), a[7]);
}

// ---- pre-pass: quantize 32 rows per block (coalesced stage through SMEM) ----
__global__ __launch_bounds__(256)
void quant_kernel(const float* __restrict__ pw)
{
    __shared__ float buf[32 * NH];            // 32 KB
    const int blk = blockIdx.x;               // NB*2*8 = 4096 blocks
    const int rb  = blk & 7;                  // 32-row block within matrix
    const int bl  = blk >> 3;                 // b*2 + l
    const float* src = pw + (size_t)bl * NH * NH + (size_t)rb * 32 * NH;
    const int tid = threadIdx.x;

    for (int idx = tid; idx < 32 * NH / 4; idx += 256)
        reinterpret_cast<float4*>(buf)[idx] =
            reinterpret_cast<const float4*>(src)[idx];
    __syncthreads();

    const int lane = tid & 31;
    const int wrp  = tid >> 5;
#pragma unroll
    for (int r = wrp * 4; r < wrp * 4 + 4; r++) {
        float mx = 0.f;
        for (int j = lane; j < NH; j += 32)
            mx = fmaxf(mx, fabsf(buf[r * NH + j]));
#pragma unroll
        for (int o = 16; o; o >>= 1)
            mx = fmaxf(mx, __shfl_xor_sync(0xffffffffu, mx, o));
        const float inv = (mx > 0.f) ? 32767.f / mx : 0.f;
        const int grow = rb * 32 + r;
        if (lane == 0)
            g_scl[bl * NH + grow] = (mx > 0.f) ? mx / 32767.f : 0.f;
        unsigned q[4];
#pragma unroll
        for (int p = 0; p < 4; p++) {
            int j = lane * 8 + p * 2;
            int va = __float2int_rn(buf[r * NH + j]     * inv);
            int vb = __float2int_rn(buf[r * NH + j + 1] * inv);
            va = max(-32767, min(32767, va)) + 32768;
            vb = max(-32767, min(32767, vb)) + 32768;
            q[p] = (unsigned)va | ((unsigned)vb << 16);
        }
        uint4 pack;
        pack.x = q[0]; pack.y = q[1]; pack.z = q[2]; pack.w = q[3];
        *reinterpret_cast<uint4*>(
            &g_pwq[((size_t)bl * NH + grow) * NH + lane * 8]) = pack;
    }
}

__global__ __launch_bounds__(256, 2)
void decoder_kernel(const float* __restrict__ y0,
                    const float* __restrict__ in_w,    // [B, C, H]
                    const float* __restrict__ in_b,    // [B, H]
                    const float* __restrict__ out_w,   // [B, H, C]
                    const float* __restrict__ out_b,   // [B, C]
                    const float* __restrict__ pb,      // [B, 2, H]
                    const float* __restrict__ cutoff,  // [1]
                    float* __restrict__ out)           // [B, C, T]
{
    __shared__ float  in_s[NC * NH];     // [c][i]
    __shared__ float  out_s[NH * NC];    // [k][c]
    __shared__ float2 act[NH];           // compacted (scaled h, row byte-offset bits)
    __shared__ __align__(16) int cnt_s[8];
    __shared__ __align__(16) float ys[NC];
    __shared__ float  po8[8 * NH];       // [group 0..7][output i] partials
    __shared__ float  po_s[256];         // out-layer partials [g16][c]
    __shared__ float  stage[NC][TB];

    const int b    = blockIdx.x;
    const int i    = threadIdx.x;
    const int lane = i & 31;
    const int wid  = i >> 5;   // warp = row group 0..7

    // ---- preload per-batch small weights into SMEM ----
    const float* inwb  = in_w  + (size_t)b * NC * NH;
    const float* outwb = out_w + (size_t)b * NH * NC;

#pragma unroll
    for (int c = 0; c < NC; c++)
        in_s[c * NH + i] = inwb[c * NH + i];

#pragma unroll
    for (int q = 0; q < 4; q++) {
        float4 v = *reinterpret_cast<const float4*>(outwb + i * NC + q * 4);
        *reinterpret_cast<float4*>(&out_s[i * NC + q * 4]) = v;
    }

    const float bin = in_b[(size_t)b * NH + i];
    const float bp0 = pb[(size_t)b * 2 * NH + i];
    const float bp1 = pb[(size_t)b * 2 * NH + NH + i];
    const float ob  = (i < NC) ? out_b[(size_t)b * NC + i] : 0.f;
    const float cut = cutoff[0];
    const float dt  = 1e-6f;
    const float s0r = g_scl[(b * 2 + 0) * NH + i];
    const float s1r = g_scl[(b * 2 + 1) * NH + i];

    if (i < NC) ys[i] = y0[(size_t)b * NC + i];

    const unsigned short* pwq0 = &g_pwq[(size_t)(b * 2 + 0) * NH * NH];
    const unsigned short* pwq1 = &g_pwq[(size_t)(b * 2 + 1) * NH * NH];
    float* outg = out + (size_t)b * NC * NT;

    int na = 0;  // active count (uniform across CTA after compact)

    // Deterministic compaction; vectorized count read (2x LDS.128).
    auto compact = [&](float rawh, float storeval, int koffbits) {
        bool nz = rawh > 0.f;
        unsigned bal = __ballot_sync(0xffffffffu, nz);
        if (lane == 0) cnt_s[wid] = __popc(bal);
        __syncthreads();
        int4 c0 = *reinterpret_cast<const int4*>(&cnt_s[0]);
        int4 c1 = *reinterpret_cast<const int4*>(&cnt_s[4]);
        na = ((c0.x + c0.y) + (c0.z + c0.w)) + ((c1.x + c1.y) + (c1.z + c1.w));
        int base = 0;
        if (wid > 0) base += c0.x;
        if (wid > 1) base += c0.y;
        if (wid > 2) base += c0.z;
        if (wid > 3) base += c0.w;
        if (wid > 4) base += c1.x;
        if (wid > 5) base += c1.y;
        if (wid > 6) base += c1.z;
        if (nz) {
            int pos = base + __popc(bal & ((1u << lane) - 1u));
            act[pos] = make_float2(storeval, __int_as_float(koffbits));
        }
        __syncthreads();
    };

    // Sparse int16 matvec, software-pipelined in 4-row chunks:
    // warp wid owns rows m ≡ wid (mod 8); thread owns outputs [lane*8 .. lane*8+7].
    // One LDG.128 per (thread,row); warp covers the full 512B int16 row contiguously.
    // Chunk c+1's act/weight loads issue before chunk c's FMA block (ping-pong bufs).
    auto prop_layer = [&](const unsigned short* wq, float bias,
                          float snext, bool last) {
        const char* bo = reinterpret_cast<const char*>(wq) + (size_t)(lane * 16);
        float a[8];
#pragma unroll
        for (int z = 0; z < 8; z++) a[z] = 0.f;

        float2 eA[4], eB[4];
        uint4  wA[4], wB[4];
        int m = wid;

        if (m + 24 < na) {
            // prologue: load chunk A at m
#pragma unroll
            for (int z = 0; z < 4; z++) eA[z] = act[m + z * 8];
#pragma unroll
            for (int z = 0; z < 4; z++)
                wA[z] = *reinterpret_cast<const uint4*>(bo + __float_as_int(eA[z].y));
            while (true) {
                int mB = m + 32;
                if (mB + 24 < na) {
                    // load chunk B, then compute A (B's latency hides under A's FMAs)
#pragma unroll
                    for (int z = 0; z < 4; z++) eB[z] = act[mB + z * 8];
#pragma unroll
                    for (int z = 0; z < 4; z++)
                        wB[z] = *reinterpret_cast<const uint4*>(bo + __float_as_int(eB[z].y));
                    rowfma_b(eA[0].x, wA[0], a);
                    rowfma_b(eA[1].x, wA[1], a);
                    rowfma_b(eA[2].x, wA[2], a);
                    rowfma_b(eA[3].x, wA[3], a);
                    corr((eA[0].x + eA[1].x) + (eA[2].x + eA[3].x), a);
                    int mA2 = mB + 32;
                    if (mA2 + 24 < na) {
#pragma unroll
                        for (int z = 0; z < 4; z++) eA[z] = act[mA2 + z * 8];
#pragma unroll
                        for (int z = 0; z < 4; z++)
                            wA[z] = *reinterpret_cast<const uint4*>(bo + __float_as_int(eA[z].y));
                        rowfma_b(eB[0].x, wB[0], a);
                        rowfma_b(eB[1].x, wB[1], a);
                        rowfma_b(eB[2].x, wB[2], a);
                        rowfma_b(eB[3].x, wB[3], a);
                        corr((eB[0].x + eB[1].x) + (eB[2].x + eB[3].x), a);
                        m = mA2;
                        continue;
                    }
                    rowfma_b(eB[0].x, wB[0], a);
                    rowfma_b(eB[1].x, wB[1], a);
                    rowfma_b(eB[2].x, wB[2], a);
                    rowfma_b(eB[3].x, wB[3], a);
                    corr((eB[0].x + eB[1].x) + (eB[2].x + eB[3].x), a);
                    m = mB + 32;
                    break;
                }
                rowfma_b(eA[0].x, wA[0], a);
                rowfma_b(eA[1].x, wA[1], a);
                rowfma_b(eA[2].x, wA[2], a);
                rowfma_b(eA[3].x, wA[3], a);
                corr((eA[0].x + eA[1].x) + (eA[2].x + eA[3].x), a);
                m = mB;
                break;
            }
        }
        for (; m < na; m += 8) {   // exact tail (<4 rows for this warp)
            float2 e = act[m];
            uint4  w = *reinterpret_cast<const uint4*>(bo + __float_as_int(e.y));
            rowfma(e.x, w, a);
        }

        // partials: outputs lane*8..+7 contiguous
        float* dst = &po8[wid * NH + lane * 8];
        float4 lo; lo.x = a[0]; lo.y = a[1]; lo.z = a[2]; lo.w = a[3];
        float4 hi; hi.x = a[4]; hi.y = a[5]; hi.z = a[6]; hi.w = a[7];
        *reinterpret_cast<float4*>(dst)     = lo;
        *reinterpret_cast<float4*>(dst + 4) = hi;
        __syncthreads();
        float h = bias;
#pragma unroll
        for (int g = 0; g < 8; g++) h += po8[g * NH + i];
        h = fmaxf(h, 0.f);
        if (last) compact(h, h, i << 10);          // raw, feeds fp32 out_s
        else      compact(h, h * snext, i << 9);   // scaled, feeds int16 layer
    };

    __syncthreads();

    for (int t = 0; t < NT; t++) {
        // ---- input layer (all SMEM; ys via 4x LDS.128) ----
        const float4* ysv = reinterpret_cast<const float4*>(ys);
        float4 y0v = ysv[0], y1v = ysv[1], y2v = ysv[2], y3v = ysv[3];
        float acc = bin;
        acc = fmaf(y0v.x, in_s[ 0 * NH + i], acc);
        acc = fmaf(y0v.y, in_s[ 1 * NH + i], acc);
        acc = fmaf(y0v.z, in_s[ 2 * NH + i], acc);
        acc = fmaf(y0v.w, in_s[ 3 * NH + i], acc);
        acc = fmaf(y1v.x, in_s[ 4 * NH + i], acc);
        acc = fmaf(y1v.y, in_s[ 5 * NH + i], acc);
        acc = fmaf(y1v.z, in_s[ 6 * NH + i], acc);
        acc = fmaf(y1v.w, in_s[ 7 * NH + i], acc);
        acc = fmaf(y2v.x, in_s[ 8 * NH + i], acc);
        acc = fmaf(y2v.y, in_s[ 9 * NH + i], acc);
        acc = fmaf(y2v.z, in_s[10 * NH + i], acc);
        acc = fmaf(y2v.w, in_s[11 * NH + i], acc);
        acc = fmaf(y3v.x, in_s[12 * NH + i], acc);
        acc = fmaf(y3v.y, in_s[13 * NH + i], acc);
        acc = fmaf(y3v.z, in_s[14 * NH + i], acc);
        acc = fmaf(y3v.w, in_s[15 * NH + i], acc);
        acc = fmaxf(acc, 0.f);
        compact(acc, acc * s0r, i << 9);   // int16 row stride = 512 B

        // ---- two prop layers (sparse int16 rows, pipelined) ----
        prop_layer(pwq0, bp0, s1r, false);
        prop_layer(pwq1, bp1, 0.f, true);

        // ---- output layer (SMEM, sparse over k) ----
        {
            int c = i & 15, g16 = i >> 4;
            float p = 0.f;
            for (int m = g16; m < na; m += 16) {
                float2 e = act[m];
                // koffbits = k<<10 -> out_s index k*16 + c = (bits>>6) + c
                p = fmaf(e.x, out_s[(__float_as_int(e.y) >> 6) + c], p);
            }
            po_s[i] = p;
        }
        __syncthreads();

        if (i < NC) {
            float f = ob;
#pragma unroll
            for (int g16 = 0; g16 < 16; g16++) f += po_s[g16 * 16 + i];
            float yn = ys[i] + cut * tanhf(dt * f / cut);
            ys[i] = yn;
            stage[i][t & (TB - 1)] = yn;
        }
        __syncthreads();

        // coalesced flush every TB steps
        if ((t & (TB - 1)) == (TB - 1) && i < NC * TB) {
            int c = i >> 3, u = i & 7;
            outg[c * NT + (t - (TB - 1)) + u] = stage[c][u];
        }
    }
}

extern "C" void kernel_launch(void* const* d_in, const int* in_sizes, int n_in,
                              void* d_out, int out_size)
{
    (void)in_sizes; (void)n_in; (void)out_size;
    quant_kernel<<<NB * 2 * 8, 256>>>((const float*)d_in[5]);  // prop_weight
    decoder_kernel<<<NB, 256>>>(
        (const float*)d_in[0],   // y0
        (const float*)d_in[1],   // in_weight
        (const float*)d_in[2],   // in_bias
        (const float*)d_in[3],   // out_weight
        (const float*)d_in[4],   // out_bias
        (const float*)d_in[6],   // prop_bias
        (const float*)d_in[7],   // cutoff
        (float*)d_out);
}

// round 15
// speedup vs baseline: 1.2027x; 1.0094x over previous
#include <cuda_runtime.h>

// Decoder: y_{t+1} = y_t + cutoff * tanh(dt * MLP_b(y_t) / cutoff), per-batch weights.
// R13 design (256x256 persistent CTAs, exact ReLU sparsity, biased PRMT dequant,
// 2-stage software-pipelined 4-row chunks) + deferred bias correction every 8 rows.
// tanhf RESTORED: the cubic approximation diverged (u = dt*f/cut reaches O(1) late in
// the trajectory; tanh saturation is load-bearing for stability).

#define NB 256
#define NC 16
#define NH 256
#define NT 1000
#define TB 8

// Quantized prop weights: biased uint16 (int16 value + 32768), layout [b][l][k][j].
__device__ __align__(16) unsigned short g_pwq[(size_t)NB * 2 * NH * NH];
__device__ float g_scl[NB * 2 * NH];   // per-row scale s = rowmax/32767

// ---- dequant helpers ----
__device__ __forceinline__ float cvlo_b(unsigned u)
{   // u16 placed in mantissa of 2^23 -> exact float 2^23 + u
    return __uint_as_float(__byte_perm(u, 0x4B000000u, 0x7410));
}
__device__ __forceinline__ float cvhi_b(unsigned u)
{
    return __uint_as_float(__byte_perm(u, 0x4B000000u, 0x7432));
}
__device__ __forceinline__ float cvlo(unsigned u) { return cvlo_b(u) - 8421376.0f; }
__device__ __forceinline__ float cvhi(unsigned u) { return cvhi_b(u) - 8421376.0f; }

// biased row FMA: 8 outputs, FFMA only (bias removed later).
__device__ __forceinline__ void rowfma_b(float e, uint4 w, float a[8])
{
    a[0] = fmaf(e, cvlo_b(w.x), a[0]);
    a[1] = fmaf(e, cvhi_b(w.x), a[1]);
    a[2] = fmaf(e, cvlo_b(w.y), a[2]);
    a[3] = fmaf(e, cvhi_b(w.y), a[3]);
    a[4] = fmaf(e, cvlo_b(w.z), a[4]);
    a[5] = fmaf(e, cvhi_b(w.z), a[5]);
    a[6] = fmaf(e, cvlo_b(w.w), a[6]);
    a[7] = fmaf(e, cvhi_b(w.w), a[7]);
}
// remove accumulated bias for a row group with activation-sum es (FFMA-imm).
__device__ __forceinline__ void corr(float es, float a[8])
{
#pragma unroll
    for (int j = 0; j < 8; j++)
        a[j] = fmaf(es, -8421376.0f, a[j]);
}
// exact row FMA for tail rows.
__device__ __forceinline__ void rowfma(float e, uint4 w, float a[8])
{
    a[0] = fmaf(e, cvlo(w.x), a[0]);
    a[1] = fmaf(e, cvhi(w.x), a[1]);
    a[2] = fmaf(e, cvlo(w.y), a[2]);
    a[3] = fmaf(e, cvhi(w.y), a[3]);
    a[4] = fmaf(e, cvlo(w.z), a[4]);
    a[5] = fmaf(e, cvhi(w.z), a[5]);
    a[6] = fmaf(e, cvlo(w.w), a[6]);
    a[7] = fmaf(e, cvhi(w.w), a[7]);
}

// ---- pre-pass: quantize 32 rows per block (coalesced stage through SMEM) ----
__global__ __launch_bounds__(256)
void quant_kernel(const float* __restrict__ pw)
{
    __shared__ float buf[32 * NH];            // 32 KB
    const int blk = blockIdx.x;               // NB*2*8 = 4096 blocks
    const int rb  = blk & 7;                  // 32-row block within matrix
    const int bl  = blk >> 3;                 // b*2 + l
    const float* src = pw + (size_t)bl * NH * NH + (size_t)rb * 32 * NH;
    const int tid = threadIdx.x;

    for (int idx = tid; idx < 32 * NH / 4; idx += 256)
        reinterpret_cast<float4*>(buf)[idx] =
            reinterpret_cast<const float4*>(src)[idx];
    __syncthreads();

    const int lane = tid & 31;
    const int wrp  = tid >> 5;
#pragma unroll
    for (int r = wrp * 4; r < wrp * 4 + 4; r++) {
        float mx = 0.f;
        for (int j = lane; j < NH; j += 32)
            mx = fmaxf(mx, fabsf(buf[r * NH + j]));
#pragma unroll
        for (int o = 16; o; o >>= 1)
            mx = fmaxf(mx, __shfl_xor_sync(0xffffffffu, mx, o));
        const float inv = (mx > 0.f) ? 32767.f / mx : 0.f;
        const int grow = rb * 32 + r;
        if (lane == 0)
            g_scl[bl * NH + grow] = (mx > 0.f) ? mx / 32767.f : 0.f;
        unsigned q[4];
#pragma unroll
        for (int p = 0; p < 4; p++) {
            int j = lane * 8 + p * 2;
            int va = __float2int_rn(buf[r * NH + j]     * inv);
            int vb = __float2int_rn(buf[r * NH + j + 1] * inv);
            va = max(-32767, min(32767, va)) + 32768;
            vb = max(-32767, min(32767, vb)) + 32768;
            q[p] = (unsigned)va | ((unsigned)vb << 16);
        }
        uint4 pack;
        pack.x = q[0]; pack.y = q[1]; pack.z = q[2]; pack.w = q[3];
        *reinterpret_cast<uint4*>(
            &g_pwq[((size_t)bl * NH + grow) * NH + lane * 8]) = pack;
    }
}

__global__ __launch_bounds__(256, 2)
void decoder_kernel(const float* __restrict__ y0,
                    const float* __restrict__ in_w,    // [B, C, H]
                    const float* __restrict__ in_b,    // [B, H]
                    const float* __restrict__ out_w,   // [B, H, C]
                    const float* __restrict__ out_b,   // [B, C]
                    const float* __restrict__ pb,      // [B, 2, H]
                    const float* __restrict__ cutoff,  // [1]
                    float* __restrict__ out)           // [B, C, T]
{
    __shared__ float  in_s[NC * NH];     // [c][i]
    __shared__ float  out_s[NH * NC];    // [k][c]
    __shared__ float2 act[NH];           // compacted (scaled h, row byte-offset bits)
    __shared__ __align__(16) int cnt_s[8];
    __shared__ __align__(16) float ys[NC];
    __shared__ float  po8[8 * NH];       // [group 0..7][output i] partials
    __shared__ float  po_s[256];         // out-layer partials [g16][c]
    __shared__ float  stage[NC][TB];

    const int b    = blockIdx.x;
    const int i    = threadIdx.x;
    const int lane = i & 31;
    const int wid  = i >> 5;   // warp = row group 0..7

    // ---- preload per-batch small weights into SMEM ----
    const float* inwb  = in_w  + (size_t)b * NC * NH;
    const float* outwb = out_w + (size_t)b * NH * NC;

#pragma unroll
    for (int c = 0; c < NC; c++)
        in_s[c * NH + i] = inwb[c * NH + i];

#pragma unroll
    for (int q = 0; q < 4; q++) {
        float4 v = *reinterpret_cast<const float4*>(outwb + i * NC + q * 4);
        *reinterpret_cast<float4*>(&out_s[i * NC + q * 4]) = v;
    }

    const float bin = in_b[(size_t)b * NH + i];
    const float bp0 = pb[(size_t)b * 2 * NH + i];
    const float bp1 = pb[(size_t)b * 2 * NH + NH + i];
    const float ob  = (i < NC) ? out_b[(size_t)b * NC + i] : 0.f;
    const float cut = cutoff[0];
    const float rcut = 1.0f / cut;
    const float dt  = 1e-6f;
    const float s0r = g_scl[(b * 2 + 0) * NH + i];
    const float s1r = g_scl[(b * 2 + 1) * NH + i];

    if (i < NC) ys[i] = y0[(size_t)b * NC + i];

    const unsigned short* pwq0 = &g_pwq[(size_t)(b * 2 + 0) * NH * NH];
    const unsigned short* pwq1 = &g_pwq[(size_t)(b * 2 + 1) * NH * NH];
    float* outg = out + (size_t)b * NC * NT;

    int na = 0;  // active count (uniform across CTA after compact)

    // Deterministic compaction; vectorized count read (2x LDS.128).
    auto compact = [&](float rawh, float storeval, int koffbits) {
        bool nz = rawh > 0.f;
        unsigned bal = __ballot_sync(0xffffffffu, nz);
        if (lane == 0) cnt_s[wid] = __popc(bal);
        __syncthreads();
        int4 c0 = *reinterpret_cast<const int4*>(&cnt_s[0]);
        int4 c1 = *reinterpret_cast<const int4*>(&cnt_s[4]);
        na = ((c0.x + c0.y) + (c0.z + c0.w)) + ((c1.x + c1.y) + (c1.z + c1.w));
        int base = 0;
        if (wid > 0) base += c0.x;
        if (wid > 1) base += c0.y;
        if (wid > 2) base += c0.z;
        if (wid > 3) base += c0.w;
        if (wid > 4) base += c1.x;
        if (wid > 5) base += c1.y;
        if (wid > 6) base += c1.z;
        if (nz) {
            int pos = base + __popc(bal & ((1u << lane) - 1u));
            act[pos] = make_float2(storeval, __int_as_float(koffbits));
        }
        __syncthreads();
    };

    // Sparse int16 matvec, software-pipelined in 4-row chunks, bias correction
    // applied once per 8 rows (A/B chunk pair). Warp wid owns rows m ≡ wid (mod 8);
    // thread owns outputs [lane*8 .. lane*8+7]. One LDG.128 per (thread,row).
    auto prop_layer = [&](const unsigned short* wq, float bias,
                          float snext, bool last) {
        const char* bo = reinterpret_cast<const char*>(wq) + (size_t)(lane * 16);
        float a[8];
#pragma unroll
        for (int z = 0; z < 8; z++) a[z] = 0.f;

        float2 eA[4], eB[4];
        uint4  wA[4], wB[4];
        int m = wid;

        if (m + 24 < na) {
            // prologue: load chunk A at m
#pragma unroll
            for (int z = 0; z < 4; z++) eA[z] = act[m + z * 8];
#pragma unroll
            for (int z = 0; z < 4; z++)
                wA[z] = *reinterpret_cast<const uint4*>(bo + __float_as_int(eA[z].y));
            while (true) {
                int mB = m + 32;
                if (mB + 24 < na) {
                    // load chunk B, then compute A (B's latency hides under A's FMAs)
#pragma unroll
                    for (int z = 0; z < 4; z++) eB[z] = act[mB + z * 8];
#pragma unroll
                    for (int z = 0; z < 4; z++)
                        wB[z] = *reinterpret_cast<const uint4*>(bo + __float_as_int(eB[z].y));
                    rowfma_b(eA[0].x, wA[0], a);
                    rowfma_b(eA[1].x, wA[1], a);
                    rowfma_b(eA[2].x, wA[2], a);
                    rowfma_b(eA[3].x, wA[3], a);
                    float esA = (eA[0].x + eA[1].x) + (eA[2].x + eA[3].x);
                    int mA2 = mB + 32;
                    if (mA2 + 24 < na) {
#pragma unroll
                        for (int z = 0; z < 4; z++) eA[z] = act[mA2 + z * 8];
#pragma unroll
                        for (int z = 0; z < 4; z++)
                            wA[z] = *reinterpret_cast<const uint4*>(bo + __float_as_int(eA[z].y));
                        rowfma_b(eB[0].x, wB[0], a);
                        rowfma_b(eB[1].x, wB[1], a);
                        rowfma_b(eB[2].x, wB[2], a);
                        rowfma_b(eB[3].x, wB[3], a);
                        // one correction for the 8-row A/B pair
                        corr(esA + ((eB[0].x + eB[1].x) + (eB[2].x + eB[3].x)), a);
                        m = mA2;
                        continue;
                    }
                    rowfma_b(eB[0].x, wB[0], a);
                    rowfma_b(eB[1].x, wB[1], a);
                    rowfma_b(eB[2].x, wB[2], a);
                    rowfma_b(eB[3].x, wB[3], a);
                    corr(esA + ((eB[0].x + eB[1].x) + (eB[2].x + eB[3].x)), a);
                    m = mB + 32;
                    break;
                }
                rowfma_b(eA[0].x, wA[0], a);
                rowfma_b(eA[1].x, wA[1], a);
                rowfma_b(eA[2].x, wA[2], a);
                rowfma_b(eA[3].x, wA[3], a);
                corr((eA[0].x + eA[1].x) + (eA[2].x + eA[3].x), a);
                m = mB;
                break;
            }
        }
        for (; m < na; m += 8) {   // exact tail (<4 rows for this warp)
            float2 e = act[m];
            uint4  w = *reinterpret_cast<const uint4*>(bo + __float_as_int(e.y));
            rowfma(e.x, w, a);
        }

        // partials: outputs lane*8..+7 contiguous
        float* dst = &po8[wid * NH + lane * 8];
        float4 lo; lo.x = a[0]; lo.y = a[1]; lo.z = a[2]; lo.w = a[3];
        float4 hi; hi.x = a[4]; hi.y = a[5]; hi.z = a[6]; hi.w = a[7];
        *reinterpret_cast<float4*>(dst)     = lo;
        *reinterpret_cast<float4*>(dst + 4) = hi;
        __syncthreads();
        float h = bias;
#pragma unroll
        for (int g = 0; g < 8; g++) h += po8[g * NH + i];
        h = fmaxf(h, 0.f);
        if (last) compact(h, h, i << 10);          // raw, feeds fp32 out_s
        else      compact(h, h * snext, i << 9);   // scaled, feeds int16 layer
    };

    __syncthreads();

    for (int t = 0; t < NT; t++) {
        // ---- input layer (all SMEM; ys via 4x LDS.128) ----
        const float4* ysv = reinterpret_cast<const float4*>(ys);
        float4 y0v = ysv[0], y1v = ysv[1], y2v = ysv[2], y3v = ysv[3];
        float acc = bin;
        acc = fmaf(y0v.x, in_s[ 0 * NH + i], acc);
        acc = fmaf(y0v.y, in_s[ 1 * NH + i], acc);
        acc = fmaf(y0v.z, in_s[ 2 * NH + i], acc);
        acc = fmaf(y0v.w, in_s[ 3 * NH + i], acc);
        acc = fmaf(y1v.x, in_s[ 4 * NH + i], acc);
        acc = fmaf(y1v.y, in_s[ 5 * NH + i], acc);
        acc = fmaf(y1v.z, in_s[ 6 * NH + i], acc);
        acc = fmaf(y1v.w, in_s[ 7 * NH + i], acc);
        acc = fmaf(y2v.x, in_s[ 8 * NH + i], acc);
        acc = fmaf(y2v.y, in_s[ 9 * NH + i], acc);
        acc = fmaf(y2v.z, in_s[10 * NH + i], acc);
        acc = fmaf(y2v.w, in_s[11 * NH + i], acc);
        acc = fmaf(y3v.x, in_s[12 * NH + i], acc);
        acc = fmaf(y3v.y, in_s[13 * NH + i], acc);
        acc = fmaf(y3v.z, in_s[14 * NH + i], acc);
        acc = fmaf(y3v.w, in_s[15 * NH + i], acc);
        acc = fmaxf(acc, 0.f);
        compact(acc, acc * s0r, i << 9);   // int16 row stride = 512 B

        // ---- two prop layers (sparse int16 rows, pipelined) ----
        prop_layer(pwq0, bp0, s1r, false);
        prop_layer(pwq1, bp1, 0.f, true);

        // ---- output layer (SMEM, sparse over k) ----
        {
            int c = i & 15, g16 = i >> 4;
            float p = 0.f;
            for (int m = g16; m < na; m += 16) {
                float2 e = act[m];
                // koffbits = k<<10 -> out_s index k*16 + c = (bits>>6) + c
                p = fmaf(e.x, out_s[(__float_as_int(e.y) >> 6) + c], p);
            }
            po_s[i] = p;
        }
        __syncthreads();

        if (i < NC) {
            float f = ob;
#pragma unroll
            for (int g16 = 0; g16 < 16; g16++) f += po_s[g16 * 16 + i];
            // tanh saturation is required for stability: u reaches O(1) late in
            // the trajectory (y drifts, f scales with ||y||). Keep tanhf.
            float yn = ys[i] + cut * tanhf(dt * f * rcut);
            ys[i] = yn;
            stage[i][t & (TB - 1)] = yn;
        }
        __syncthreads();

        // coalesced flush every TB steps
        if ((t & (TB - 1)) == (TB - 1) && i < NC * TB) {
            int c = i >> 3, u = i & 7;
            outg[c * NT + (t - (TB - 1)) + u] = stage[c][u];
        }
    }
}

extern "C" void kernel_launch(void* const* d_in, const int* in_sizes, int n_in,
                              void* d_out, int out_size)
{
    (void)in_sizes; (void)n_in; (void)out_size;
    quant_kernel<<<NB * 2 * 8, 256>>>((const float*)d_in[5]);  // prop_weight
    decoder_kernel<<<NB, 256>>>(
        (const float*)d_in[0],   // y0
        (const float*)d_in[1],   // in_weight
        (const float*)d_in[2],   // in_bias
        (const float*)d_in[3],   // out_weight
        (const float*)d_in[4],   // out_bias
        (const float*)d_in[6],   // prop_bias
        (const float*)d_in[7],   // cutoff
        (float*)d_out);
}